// round 16
// baseline (speedup 1.0000x reference)
#include <cuda_runtime.h>
#include <cuda_fp16.h>
#include <cstdint>

#define NN 100000
#define EO 600000
#define EL 1200000
#define HD 128
#define OD 64
#define SA 136   // smem row stride (fp16 elems); 272B rows, 16B aligned

// ---------------- scratch (device globals) ---------------------------------
static __device__ __half g_hA[(size_t)NN * HD];
static __device__ __half g_hB[(size_t)NN * HD];
static __device__ __half g_hC[(size_t)NN * HD];
static __device__ __half g_hD[(size_t)NN * HD];
static __device__ __half g_heA[(size_t)EO * HD];
static __device__ __half g_heB[(size_t)EO * HD];
static __device__ __half g_heC[(size_t)EO * HD];
static __device__ __half g_W1h[5][HD * HD];          // n-major fp16 images
static __device__ __half g_W2h[5][HD * HD];
static __device__ uint32_t g_W1F[5][8192];           // W1 frags (N=128)
static __device__ uint32_t g_W2F[5][8192];           // W2 frags (N=128)
static __device__ uint32_t g_Wofh[4096], g_Wofl[4096];  // Wo frags hi+lo (N=64)
static __device__ float g_bfb[5][HD];
// CSR scratch
static __device__ int g_deg[EO], g_ex[EO], g_bsum[1024];
static __device__ int g_rpN[NN + 1], g_adjN[EO], g_curN[NN];
static __device__ int g_rpE[EO + 1], g_adjE[EL], g_curE[EO];

// ---------------- PTX helpers ----------------------------------------------
__device__ __forceinline__ void ldsm4(uint32_t* r, const void* p) {
    uint32_t a = (uint32_t)__cvta_generic_to_shared(p);
    asm volatile("ldmatrix.sync.aligned.m8n8.x4.shared.b16 {%0,%1,%2,%3}, [%4];"
                 : "=r"(r[0]), "=r"(r[1]), "=r"(r[2]), "=r"(r[3]) : "r"(a));
}
__device__ __forceinline__ void stsm4(void* p, uint32_t r0, uint32_t r1,
                                      uint32_t r2, uint32_t r3) {
    uint32_t a = (uint32_t)__cvta_generic_to_shared(p);
    asm volatile("stmatrix.sync.aligned.m8n8.x4.shared.b16 [%0], {%1,%2,%3,%4};"
                 :: "r"(a), "r"(r0), "r"(r1), "r"(r2), "r"(r3) : "memory");
}
__device__ __forceinline__ void mma_f16(float* d, const uint32_t* a,
                                        uint32_t b0, uint32_t b1) {
    asm volatile(
        "mma.sync.aligned.m16n8k16.row.col.f32.f16.f16.f32 "
        "{%0,%1,%2,%3}, {%4,%5,%6,%7}, {%8,%9}, {%0,%1,%2,%3};"
        : "+f"(d[0]), "+f"(d[1]), "+f"(d[2]), "+f"(d[3])
        : "r"(a[0]), "r"(a[1]), "r"(a[2]), "r"(a[3]), "r"(b0), "r"(b1));
}
__device__ __forceinline__ void cp16(void* sdst, const void* gsrc) {
    uint32_t a = (uint32_t)__cvta_generic_to_shared(sdst);
    asm volatile("cp.async.cg.shared.global [%0], [%1], 16;"
                 :: "r"(a), "l"(gsrc) : "memory");
}
#define CP_COMMIT() asm volatile("cp.async.commit_group;" ::: "memory")
#define CP_WAIT0()  asm volatile("cp.async.wait_group 0;" ::: "memory")

__device__ __forceinline__ uint32_t packh(float a, float b) {
    __half2 t = __floats2half2_rn(a, b);
    return *(uint32_t*)&t;
}
__device__ __forceinline__ void unpackh(uint32_t v, float& a, float& b) {
    __half2 t = *(__half2*)&v;
    a = __half2float(__low2half(t));
    b = __half2float(__high2half(t));
}
#define BARQ(id) asm volatile("bar.sync %0, 128;" :: "r"(id) : "memory")

// ---------------- GEMM pass: A fp16 from smem, W single-fp16 frags ----------
__device__ __forceinline__ void gemm_pass_frag(
    const __half* As, const uint4* __restrict__ F,
    int cc, int lrow, int lkoff, int lane, float (&acc)[2][4][4]) {
#pragma unroll
    for (int mi = 0; mi < 2; ++mi)
#pragma unroll
        for (int ni = 0; ni < 4; ++ni)
#pragma unroll
            for (int q = 0; q < 4; ++q) acc[mi][ni][q] = 0.f;
#pragma unroll
    for (int ks = 0; ks < 8; ++ks) {
        const int k0 = ks * 16 + lkoff;
        uint32_t ah[2][4];
#pragma unroll
        for (int mi = 0; mi < 2; ++mi)
            ldsm4(ah[mi], As + (mi * 16 + lrow) * SA + k0);
#pragma unroll
        for (int nj = 0; nj < 2; ++nj) {
            const uint4 b = F[((cc * 2 + nj) * 8 + ks) * 32 + lane];
#pragma unroll
            for (int mi = 0; mi < 2; ++mi) {
                const int n0 = nj * 2;
                mma_f16(acc[mi][n0], ah[mi], b.x, b.z);
                mma_f16(acc[mi][n0 + 1], ah[mi], b.y, b.w);
            }
        }
    }
}

// bias+relu then stmatrix back into As (quarter rows 0..31)
__device__ __forceinline__ void epi_to_smem(
    const float (&acc)[2][4][4], const float (&br)[4][2],
    __half* As, int colBase, int lane) {
    const int srow = (lane & 7) + ((lane >> 3) & 1) * 8;
    const int scol = (lane >> 4) * 8;
#pragma unroll
    for (int mi = 0; mi < 2; ++mi) {
#pragma unroll
        for (int ng = 0; ng < 2; ++ng) {
            float v[2][4];
#pragma unroll
            for (int q = 0; q < 2; ++q) {
                const int ni = ng * 2 + q;
                v[q][0] = fmaxf(acc[mi][ni][0] + br[ni][0], 0.f);
                v[q][1] = fmaxf(acc[mi][ni][1] + br[ni][1], 0.f);
                v[q][2] = fmaxf(acc[mi][ni][2] + br[ni][0], 0.f);
                v[q][3] = fmaxf(acc[mi][ni][3] + br[ni][1], 0.f);
            }
            const int off = (mi * 16 + srow) * SA + colBase + ng * 16 + scol;
            stsm4(As + off, packh(v[0][0], v[0][1]), packh(v[0][2], v[0][3]),
                  packh(v[1][0], v[1][1]), packh(v[1][2], v[1][3]));
        }
    }
}

// gmem write: acc + bias + relu -> C [M,HD] as fp16
__device__ __forceinline__ void write_outh(
    const float (&acc)[2][4][4], const float (&br)[4][2],
    __half* __restrict__ C, int m0, int colBase, int cq, int rq, int M) {
#pragma unroll
    for (int mi = 0; mi < 2; ++mi)
#pragma unroll
        for (int ni = 0; ni < 4; ++ni) {
            const int col = colBase + ni * 8 + cq;
            const int r0 = m0 + mi * 16 + rq, r1 = r0 + 8;
            float v00 = fmaxf(acc[mi][ni][0] + br[ni][0], 0.f);
            float v01 = fmaxf(acc[mi][ni][1] + br[ni][1], 0.f);
            float v10 = fmaxf(acc[mi][ni][2] + br[ni][0], 0.f);
            float v11 = fmaxf(acc[mi][ni][3] + br[ni][1], 0.f);
            if (r0 < M) *(uint32_t*)(C + (size_t)r0 * HD + col) = packh(v00, v01);
            if (r1 < M) *(uint32_t*)(C + (size_t)r1 * HD + col) = packh(v10, v11);
        }
}

// smem: per quarter: two ping-pong As buffers (8704 B each) = 17408; x4
#define QSZ    17408
#define SMEM_F 69632

// cp.async a 32-row fp16 tile straight into ldsm layout (row*SA)
__device__ __forceinline__ void issue_cp_tileh(const __half* __restrict__ A,
                                               __half* Asdst, int tile, int M,
                                               int tiq) {
#pragma unroll
    for (int qq = 0; qq < 4; ++qq) {
        const int i = tiq + 128 * qq;         // 0..511
        const int r = i >> 4, c = i & 15;     // 16 x 16B chunks per 256B row
        const int grow = tile * 32 + r;
        __half* dst = Asdst + r * SA + c * 8;
        if (grow < M)
            cp16(dst, A + (size_t)grow * HD + c * 8);
        else
            *(uint4*)dst = make_uint4(0, 0, 0, 0);
    }
}

// ---------------- fused GIN layer: 4 independent quarter-pipelines ----------
// HEAD=false: out fp16 [M,HD]; HEAD=true: third GEMM vs Wo (hi+lo), out f32
template <bool HEAD>
__global__ __launch_bounds__(512, 1) void fused_gin(
    const __half* __restrict__ A,
    const uint4* __restrict__ W1F, const uint4* __restrict__ W2F,
    const uint4* __restrict__ WoFh, const uint4* __restrict__ WoFl,
    const float* __restrict__ b1, const float* __restrict__ b2,
    const float* __restrict__ b3,
    __half* __restrict__ C, float* __restrict__ Cf, int M, int nTiles) {
    extern __shared__ char smem[];
    const int tid = threadIdx.x, lane = tid & 31, wid = tid >> 5;
    const int q = wid >> 2, cc = wid & 3, tiq = tid & 127;

    __half* As0 = (__half*)(smem + q * QSZ);
    __half* As1 = As0 + 32 * SA;

    const int barid = 1 + q;
    const int colBase = cc * 32;
    const int lrow = lane & 15, lkoff = (lane >> 4) * 8;
    const int cq = (lane & 3) * 2, rq = lane >> 2;

    float b1r[4][2], b2r[4][2], b3r[2][2];
#pragma unroll
    for (int ni = 0; ni < 4; ++ni) {
        const int col = colBase + ni * 8 + cq;
        b1r[ni][0] = b1[col]; b1r[ni][1] = b1[col + 1];
        b2r[ni][0] = b2[col]; b2r[ni][1] = b2[col + 1];
    }
    if (HEAD) {
#pragma unroll
        for (int ni = 0; ni < 2; ++ni) {
            const int col = cc * 16 + ni * 8 + cq;
            b3r[ni][0] = b3[col]; b3r[ni][1] = b3[col + 1];
        }
    }

    int tile = blockIdx.x * 4 + q;
    int pb = 0;
    if (tile < nTiles) issue_cp_tileh(A, As0, tile, M, tiq);
    CP_COMMIT();

    for (; tile < nTiles; tile += gridDim.x * 4) {
        const int m0 = tile * 32;
        __half* Asb = pb ? As1 : As0;
        __half* Aso = pb ? As0 : As1;
        CP_WAIT0();
        BARQ(barid);   // this tile's A landed; previous iteration fully done

        const int nxt = tile + gridDim.x * 4;
        if (nxt < nTiles) issue_cp_tileh(A, Aso, nxt, M, tiq);
        CP_COMMIT();

        float acc[2][4][4];
        gemm_pass_frag(Asb, W1F, cc, lrow, lkoff, lane, acc);
        BARQ(barid);
        epi_to_smem(acc, b1r, Asb, colBase, lane);
        BARQ(barid);
        gemm_pass_frag(Asb, W2F, cc, lrow, lkoff, lane, acc);

        if (!HEAD) {
            write_outh(acc, b2r, C, m0, colBase, cq, rq, M);
        } else {
            BARQ(barid);
            epi_to_smem(acc, b2r, Asb, colBase, lane);
            BARQ(barid);
            float acc3[2][2][4];
#pragma unroll
            for (int mi = 0; mi < 2; ++mi)
#pragma unroll
                for (int ni = 0; ni < 2; ++ni)
#pragma unroll
                    for (int p = 0; p < 4; ++p) acc3[mi][ni][p] = 0.f;
#pragma unroll
            for (int ks = 0; ks < 8; ++ks) {
                const int k0 = ks * 16 + lkoff;
                uint32_t ah[2][4];
#pragma unroll
                for (int mi = 0; mi < 2; ++mi)
                    ldsm4(ah[mi], Asb + (mi * 16 + lrow) * SA + k0);
                const uint4 bh = WoFh[(cc * 8 + ks) * 32 + lane];
                const uint4 bl = WoFl[(cc * 8 + ks) * 32 + lane];
#pragma unroll
                for (int mi = 0; mi < 2; ++mi) {
                    mma_f16(acc3[mi][0], ah[mi], bh.x, bh.z);
                    mma_f16(acc3[mi][0], ah[mi], bl.x, bl.z);
                    mma_f16(acc3[mi][1], ah[mi], bh.y, bh.w);
                    mma_f16(acc3[mi][1], ah[mi], bl.y, bl.w);
                }
            }
#pragma unroll
            for (int mi = 0; mi < 2; ++mi)
#pragma unroll
                for (int ni = 0; ni < 2; ++ni) {
                    const int col = cc * 16 + ni * 8 + cq;
                    const int r0 = m0 + mi * 16 + rq, r1 = r0 + 8;
                    if (r0 < M)
                        *(float2*)(Cf + (size_t)r0 * OD + col) = make_float2(
                            acc3[mi][ni][0] + b3r[ni][0], acc3[mi][ni][1] + b3r[ni][1]);
                    if (r1 < M)
                        *(float2*)(Cf + (size_t)r1 * OD + col) = make_float2(
                            acc3[mi][ni][2] + b3r[ni][0], acc3[mi][ni][3] + b3r[ni][1]);
                }
        }
        pb ^= 1;
    }
}

// ---------------- fused node layer 1 + MLP (4 passes) ----------------------
__global__ __launch_bounds__(512, 1) void fused_gin_mlp(
    const __half* __restrict__ A,
    const uint4* __restrict__ WaF, const uint4* __restrict__ WbF,
    const uint4* __restrict__ WcF, const uint4* __restrict__ WdF,
    const float* __restrict__ b1, const float* __restrict__ b2,
    const float* __restrict__ b3, const float* __restrict__ b4,
    __half* __restrict__ C, int M, int nTiles) {
    extern __shared__ char smem[];
    const int tid = threadIdx.x, lane = tid & 31, wid = tid >> 5;
    const int q = wid >> 2, cc = wid & 3, tiq = tid & 127;

    __half* As0 = (__half*)(smem + q * QSZ);
    __half* As1 = As0 + 32 * SA;

    const int barid = 1 + q;
    const int colBase = cc * 32;
    const int lrow = lane & 15, lkoff = (lane >> 4) * 8;
    const int cq = (lane & 3) * 2, rq = lane >> 2;

    float b1r[4][2], b2r[4][2], b3r[4][2], b4r[4][2];
#pragma unroll
    for (int ni = 0; ni < 4; ++ni) {
        const int col = colBase + ni * 8 + cq;
        b1r[ni][0] = b1[col]; b1r[ni][1] = b1[col + 1];
        b2r[ni][0] = b2[col]; b2r[ni][1] = b2[col + 1];
        b3r[ni][0] = b3[col]; b3r[ni][1] = b3[col + 1];
        b4r[ni][0] = b4[col]; b4r[ni][1] = b4[col + 1];
    }

    int tile = blockIdx.x * 4 + q;
    int pb = 0;
    if (tile < nTiles) issue_cp_tileh(A, As0, tile, M, tiq);
    CP_COMMIT();

    for (; tile < nTiles; tile += gridDim.x * 4) {
        const int m0 = tile * 32;
        __half* Asb = pb ? As1 : As0;
        __half* Aso = pb ? As0 : As1;
        CP_WAIT0();
        BARQ(barid);

        const int nxt = tile + gridDim.x * 4;
        if (nxt < nTiles) issue_cp_tileh(A, Aso, nxt, M, tiq);
        CP_COMMIT();

        float acc[2][4][4];
        gemm_pass_frag(Asb, WaF, cc, lrow, lkoff, lane, acc);
        BARQ(barid);
        epi_to_smem(acc, b1r, Asb, colBase, lane);
        BARQ(barid);
        gemm_pass_frag(Asb, WbF, cc, lrow, lkoff, lane, acc);
        BARQ(barid);
        epi_to_smem(acc, b2r, Asb, colBase, lane);   // layer out (relu)
        BARQ(barid);
        gemm_pass_frag(Asb, WcF, cc, lrow, lkoff, lane, acc);
        BARQ(barid);
        epi_to_smem(acc, b3r, Asb, colBase, lane);   // mlp hidden (relu)
        BARQ(barid);
        gemm_pass_frag(Asb, WdF, cc, lrow, lkoff, lane, acc);
        // mlp out (no relu) -> fp16
#pragma unroll
        for (int mi = 0; mi < 2; ++mi)
#pragma unroll
            for (int ni = 0; ni < 4; ++ni) {
                const int col = colBase + ni * 8 + cq;
                const int r0 = m0 + mi * 16 + rq, r1 = r0 + 8;
                if (r0 < M)
                    *(uint32_t*)(C + (size_t)r0 * HD + col) =
                        packh(acc[mi][ni][0] + b4r[ni][0], acc[mi][ni][1] + b4r[ni][1]);
                if (r1 < M)
                    *(uint32_t*)(C + (size_t)r1 * HD + col) =
                        packh(acc[mi][ni][2] + b4r[ni][0], acc[mi][ni][3] + b4r[ni][1]);
            }
        pb ^= 1;
    }
}

// ---------------- weight prep ------------------------------------------------
struct PrepArgs {
    const float *W1[5], *b1[5], *g[5], *bb[5], *m[5], *v[5], *W2[5], *Wo;
    __half *W1h[5], *W2h[5];
    uint32_t *Wofh, *Wofl;
    float* bf[5];
};

__global__ void prep_weights(PrepArgs a) {
    const int blk = blockIdx.x, tid = threadIdx.x;
    if (blk < 320) {
        const int j = blk >> 6;
        const int idx = ((blk & 63) << 8) + tid;
        const int k = idx >> 7, n = idx & 127;
        float s = a.g[j][n] * rsqrtf(a.v[j][n] + 1e-5f);
        a.W1h[j][n * 128 + k] = __float2half(a.W1[j][idx] * s);
        if (idx < 128)
            a.bf[j][idx] = a.b1[j][idx] * s + a.bb[j][idx] - a.m[j][idx] * s;
    } else if (blk < 640) {
        const int j = (blk - 320) >> 6;
        const int idx = (((blk - 320) & 63) << 8) + tid;
        const int k = idx >> 7, n = idx & 127;
        a.W2h[j][n * 128 + k] = __float2half(a.W2[j][idx]);
    } else {
        const int idx = ((blk - 640) << 8) + tid;  // 0..4095 (Wo frags hi+lo)
        const int j = idx & 3, L = (idx >> 2) & 31;
        const int ks = (idx >> 7) & 7, cc = idx >> 10;
        const int n = cc * 16 + (j & 1) * 8 + (L >> 2);
        const int k = ks * 16 + ((j >> 1)) * 8 + (L & 3) * 2;
        float v0 = a.Wo[k * OD + n];
        float v1 = a.Wo[(k + 1) * OD + n];
        __half h0 = __float2half(v0), h1 = __float2half(v1);
        __half l0 = __float2half(v0 - __half2float(h0));
        __half l1 = __float2half(v1 - __half2float(h1));
        __half2 th = __halves2half2(h0, h1), tl = __halves2half2(l0, l1);
        a.Wofh[((cc * 8 + ks) * 32 + L) * 4 + j] = *(uint32_t*)&th;
        a.Wofl[((cc * 8 + ks) * 32 + L) * 4 + j] = *(uint32_t*)&tl;
    }
}

struct FragArgs {
    const __half* src[10];
    uint32_t* dst[10];
};
__global__ void frag_all(FragArgs a) {
    const int i = blockIdx.x * 256 + threadIdx.x;   // 0..81919
    const int m = i >> 13, e = i & 8191;
    const int j = e & 3, L = (e >> 2) & 31;
    const int ks = (e >> 7) & 7, g = e >> 10;
    const int n = g * 16 + (j & 1) * 8 + (L >> 2);
    const int k = ks * 16 + (j >> 1) * 8 + (L & 3) * 2;
    a.dst[m][e] = *(const uint32_t*)(a.src[m] + n * 128 + k);
}

// ---------------- CSR build ----------------------------------------------------
__global__ void count_deg(const int* __restrict__ dst, int E, int* __restrict__ deg) {
    int e = blockIdx.x * 256 + threadIdx.x;
    if (e < E) atomicAdd(&deg[dst[e]], 1);
}

__global__ void scan1(const int* __restrict__ deg, int* __restrict__ ex,
                      int* __restrict__ bsum, int n) {
    __shared__ int wsum[32];
    const int t = threadIdx.x;
    const int base = blockIdx.x * 4096 + t * 4;
    int v[4], s = 0;
#pragma unroll
    for (int i = 0; i < 4; ++i) {
        int idx = base + i;
        v[i] = idx < n ? deg[idx] : 0;
        s += v[i];
    }
    const int lane = t & 31, w = t >> 5;
    int ps = s;
#pragma unroll
    for (int o = 1; o < 32; o <<= 1) {
        int y = __shfl_up_sync(~0u, ps, o);
        if (lane >= o) ps += y;
    }
    if (lane == 31) wsum[w] = ps;
    __syncthreads();
    if (w == 0) {
        int x = wsum[lane];
#pragma unroll
        for (int o = 1; o < 32; o <<= 1) {
            int y = __shfl_up_sync(~0u, x, o);
            if (lane >= o) x += y;
        }
        wsum[lane] = x;
    }
    __syncthreads();
    const int warpoff = w ? wsum[w - 1] : 0;
    int run = warpoff + ps - s;
#pragma unroll
    for (int i = 0; i < 4; ++i) {
        int idx = base + i;
        if (idx < n) ex[idx] = run;
        run += v[i];
    }
    if (t == 0) bsum[blockIdx.x] = wsum[31];
}

__global__ void scan2(int* __restrict__ bsum, int nb) {
    __shared__ int sm_[1024];
    const int t = threadIdx.x;
    int v = (t < nb) ? bsum[t] : 0;
    sm_[t] = v;
    __syncthreads();
    for (int o = 1; o < 1024; o <<= 1) {
        int y = (t >= o) ? sm_[t - o] : 0;
        __syncthreads();
        sm_[t] += y;
        __syncthreads();
    }
    if (t < nb) bsum[t] = sm_[t] - v;
}

__global__ void scan3(const int* __restrict__ ex, const int* __restrict__ boff,
                      int* __restrict__ rp, int* __restrict__ cur, int n, int E) {
    int i = blockIdx.x * 1024 + threadIdx.x;
    if (i < n) {
        int vv = ex[i] + boff[i >> 12];
        rp[i] = vv;
        cur[i] = vv;
    } else if (i == n) {
        rp[n] = E;
    }
}

__global__ void fill_csr(const int* __restrict__ src, const int* __restrict__ dst,
                         int E, int* __restrict__ cur, int* __restrict__ adj) {
    int e = blockIdx.x * 256 + threadIdx.x;
    if (e < E) {
        int p = atomicAdd(&cur[dst[e]], 1);
        adj[p] = src[e];
    }
}

// ---------------- gather aggregation (fp16 rows, f32 accumulate) --------------
__device__ __forceinline__ void addrow_h(const __half* __restrict__ x, int row,
                                         int lane, float (&acc)[4]) {
    uint2 u = *(const uint2*)(x + (size_t)row * HD + lane * 4);
    float a0, a1, a2, a3;
    unpackh(u.x, a0, a1);
    unpackh(u.y, a2, a3);
    acc[0] += a0; acc[1] += a1; acc[2] += a2; acc[3] += a3;
}

// first layer: x f32, out fp16
__global__ void gather_agg_f(const float* __restrict__ x,
                             const int* __restrict__ rp,
                             const int* __restrict__ adj,
                             __half* __restrict__ agg, int n) {
    unsigned t = blockIdx.x * 256u + threadIdx.x;
    unsigned r = t >> 5, lane = t & 31u;
    if (r >= (unsigned)n) return;
    const int s = rp[r], e = rp[r + 1];
    float4 acc = ((const float4*)(x + (size_t)r * HD))[lane];
    const int cnt = e - s;
    int nb_l = ((int)lane < cnt) ? adj[s + lane] : 0;
    const int lim = cnt < 32 ? cnt : 32;
    for (int j = 0; j < lim; ++j) {
        const int nb = __shfl_sync(~0u, nb_l, j);
        float4 u = ((const float4*)(x + (size_t)nb * HD))[lane];
        acc.x += u.x; acc.y += u.y; acc.z += u.z; acc.w += u.w;
    }
    for (int j = s + 32; j < e; ++j) {
        const int nb = adj[j];
        float4 u = ((const float4*)(x + (size_t)nb * HD))[lane];
        acc.x += u.x; acc.y += u.y; acc.z += u.z; acc.w += u.w;
    }
    *(uint2*)(agg + (size_t)r * HD + lane * 4) =
        make_uint2(packh(acc.x, acc.y), packh(acc.z, acc.w));
}

// fp16 in, fp16 out
__global__ void gather_agg_h(const __half* __restrict__ x,
                             const int* __restrict__ rp,
                             const int* __restrict__ adj,
                             __half* __restrict__ agg, int n) {
    unsigned t = blockIdx.x * 256u + threadIdx.x;
    unsigned r = t >> 5, lane = t & 31u;
    if (r >= (unsigned)n) return;
    const int s = rp[r], e = rp[r + 1];
    float acc[4] = {0.f, 0.f, 0.f, 0.f};
    addrow_h(x, r, lane, acc);
    const int cnt = e - s;
    int nb_l = ((int)lane < cnt) ? adj[s + lane] : 0;
    const int lim = cnt < 32 ? cnt : 32;
    for (int j = 0; j < lim; ++j) {
        const int nb = __shfl_sync(~0u, nb_l, j);
        addrow_h(x, nb, lane, acc);
    }
    for (int j = s + 32; j < e; ++j) addrow_h(x, adj[j], lane, acc);
    *(uint2*)(agg + (size_t)r * HD + lane * 4) =
        make_uint2(packh(acc[0], acc[1]), packh(acc[2], acc[3]));
}

// fused pair lift + aggregation (fp16 y, L2-resident)
__global__ void pair_agg_h(const int* __restrict__ ep,
                           const __half* __restrict__ y,
                           const int* __restrict__ rp,
                           const int* __restrict__ adj,
                           __half* __restrict__ agg, int n) {
    unsigned t = blockIdx.x * 256u + threadIdx.x;
    unsigned r = t >> 5, lane = t & 31u;
    if (r >= (unsigned)n) return;
    const int s = rp[r], e = rp[r + 1];
    const int cnt = e - s;
    float acc[4] = {0.f, 0.f, 0.f, 0.f};
    addrow_h(y, ep[2 * r], lane, acc);
    addrow_h(y, ep[2 * r + 1], lane, acc);
    int p0_l = 0, p1_l = 0;
    if ((int)lane < cnt) {
        const int nb = adj[s + lane];
        p0_l = ep[2 * nb];
        p1_l = ep[2 * nb + 1];
    }
    const int lim = cnt < 32 ? cnt : 32;
    for (int j = 0; j < lim; ++j) {
        addrow_h(y, __shfl_sync(~0u, p0_l, j), lane, acc);
        addrow_h(y, __shfl_sync(~0u, p1_l, j), lane, acc);
    }
    for (int j = s + 32; j < e; ++j) {
        const int nb = adj[j];
        addrow_h(y, ep[2 * nb], lane, acc);
        addrow_h(y, ep[2 * nb + 1], lane, acc);
    }
    *(uint2*)(agg + (size_t)r * HD + lane * 4) =
        make_uint2(packh(acc[0], acc[1]), packh(acc[2], acc[3]));
}

// ----------------------------------------------------------------------------------
extern "C" void kernel_launch(void* const* d_in, const int* in_sizes, int n_in,
                              void* d_out, int out_size) {
    const int*   edge_index = (const int*)d_in[0];
    const float* x_orig     = (const float*)d_in[1];
    const int*   ei_orig    = (const int*)d_in[2];
    const int*   edge_pairs = (const int*)d_in[3];
    const float* init_W1 = (const float*)d_in[4];
    const float* init_b1 = (const float*)d_in[5];
    const float* init_g  = (const float*)d_in[6];
    const float* init_bb = (const float*)d_in[7];
    const float* init_m  = (const float*)d_in[8];
    const float* init_v  = (const float*)d_in[9];
    const float* init_W2 = (const float*)d_in[10];
    const float* init_b2 = (const float*)d_in[11];
    const float* gin_W1  = (const float*)d_in[12];
    const float* gin_b1  = (const float*)d_in[13];
    const float* gin_g   = (const float*)d_in[14];
    const float* gin_bb  = (const float*)d_in[15];
    const float* gin_m   = (const float*)d_in[16];
    const float* gin_v   = (const float*)d_in[17];
    const float* gin_W2  = (const float*)d_in[18];
    const float* gin_b2  = (const float*)d_in[19];
    const float* mlp_W1  = (const float*)d_in[20];
    const float* mlp_b1  = (const float*)d_in[21];
    const float* mlp_g   = (const float*)d_in[22];
    const float* mlp_bb  = (const float*)d_in[23];
    const float* mlp_m   = (const float*)d_in[24];
    const float* mlp_v   = (const float*)d_in[25];
    const float* mlp_W2  = (const float*)d_in[26];
    const float* mlp_b2  = (const float*)d_in[27];
    const float* out_W   = (const float*)d_in[28];
    const float* out_b   = (const float*)d_in[29];
    float* out = (float*)d_out;

    __half *hA, *hB, *hC, *hD, *heA, *heB, *heC;
    __half *W1h, *W2h;
    uint32_t *W1F, *W2F, *Wofh, *Wofl;
    float* bfb;
    int *deg, *ex, *bsum, *rpN, *adjN, *curN, *rpE, *adjE, *curE;
    cudaGetSymbolAddress((void**)&hA, g_hA);
    cudaGetSymbolAddress((void**)&hB, g_hB);
    cudaGetSymbolAddress((void**)&hC, g_hC);
    cudaGetSymbolAddress((void**)&hD, g_hD);
    cudaGetSymbolAddress((void**)&heA, g_heA);
    cudaGetSymbolAddress((void**)&heB, g_heB);
    cudaGetSymbolAddress((void**)&heC, g_heC);
    cudaGetSymbolAddress((void**)&bfb, g_bfb);
    cudaGetSymbolAddress((void**)&W1h, g_W1h);
    cudaGetSymbolAddress((void**)&W2h, g_W2h);
    cudaGetSymbolAddress((void**)&W1F, g_W1F);
    cudaGetSymbolAddress((void**)&W2F, g_W2F);
    cudaGetSymbolAddress((void**)&Wofh, g_Wofh);
    cudaGetSymbolAddress((void**)&Wofl, g_Wofl);
    cudaGetSymbolAddress((void**)&deg, g_deg);
    cudaGetSymbolAddress((void**)&ex, g_ex);
    cudaGetSymbolAddress((void**)&bsum, g_bsum);
    cudaGetSymbolAddress((void**)&rpN, g_rpN);
    cudaGetSymbolAddress((void**)&adjN, g_adjN);
    cudaGetSymbolAddress((void**)&curN, g_curN);
    cudaGetSymbolAddress((void**)&rpE, g_rpE);
    cudaGetSymbolAddress((void**)&adjE, g_adjE);
    cudaGetSymbolAddress((void**)&curE, g_curE);

    // ---- weight prep --------------------------------------------------------
    PrepArgs pa;
    const float* W1s[5]  = {init_W1, init_W1 + HD * HD, mlp_W1, gin_W1, gin_W1 + HD * HD};
    const float* b1s[5]  = {init_b1, init_b1 + HD, mlp_b1, gin_b1, gin_b1 + HD};
    const float* gs[5]   = {init_g, init_g + HD, mlp_g, gin_g, gin_g + HD};
    const float* bbs[5]  = {init_bb, init_bb + HD, mlp_bb, gin_bb, gin_bb + HD};
    const float* ms[5]   = {init_m, init_m + HD, mlp_m, gin_m, gin_m + HD};
    const float* vs[5]   = {init_v, init_v + HD, mlp_v, gin_v, gin_v + HD};
    const float* W2s[5]  = {init_W2, init_W2 + HD * HD, mlp_W2, gin_W2, gin_W2 + HD * HD};
    for (int j = 0; j < 5; ++j) {
        pa.W1[j] = W1s[j]; pa.b1[j] = b1s[j]; pa.g[j] = gs[j]; pa.bb[j] = bbs[j];
        pa.m[j] = ms[j]; pa.v[j] = vs[j]; pa.W2[j] = W2s[j];
        pa.W1h[j] = W1h + (size_t)j * HD * HD;
        pa.W2h[j] = W2h + (size_t)j * HD * HD;
        pa.bf[j] = bfb + j * HD;
    }
    pa.Wo = out_W; pa.Wofh = Wofh; pa.Wofl = Wofl;
    prep_weights<<<656, 256>>>(pa);

    FragArgs fa;
    for (int j = 0; j < 5; ++j) {
        fa.src[j]     = W1h + (size_t)j * HD * HD; fa.dst[j]     = W1F + (size_t)j * 8192;
        fa.src[5 + j] = W2h + (size_t)j * HD * HD; fa.dst[5 + j] = W2F + (size_t)j * 8192;
    }
    frag_all<<<320, 256>>>(fa);

    // ---- CSR build: node graph --------------------------------------------
    cudaMemsetAsync(deg, 0, NN * sizeof(int));
    count_deg<<<(EO + 255) / 256, 256>>>(ei_orig + EO, EO, deg);
    scan1<<<(NN + 4095) / 4096, 1024>>>(deg, ex, bsum, NN);
    scan2<<<1, 1024>>>(bsum, (NN + 4095) / 4096);
    scan3<<<(NN + 1024) / 1024 + 1, 1024>>>(ex, bsum, rpN, curN, NN, EO);
    fill_csr<<<(EO + 255) / 256, 256>>>(ei_orig, ei_orig + EO, EO, curN, adjN);

    // ---- CSR build: line graph --------------------------------------------
    cudaMemsetAsync(deg, 0, EO * sizeof(int));
    count_deg<<<(EL + 255) / 256, 256>>>(edge_index + EL, EL, deg);
    scan1<<<(EO + 4095) / 4096, 1024>>>(deg, ex, bsum, EO);
    scan2<<<1, 1024>>>(bsum, (EO + 4095) / 4096);
    scan3<<<(EO + 1024) / 1024 + 1, 1024>>>(ex, bsum, rpE, curE, EO, EL);
    fill_csr<<<(EL + 255) / 256, 256>>>(edge_index, edge_index + EL, EL, curE, adjE);

    // ---- main pipeline ------------------------------------------------------
    cudaFuncSetAttribute(fused_gin<false>,
                         cudaFuncAttributeMaxDynamicSharedMemorySize, SMEM_F);
    cudaFuncSetAttribute(fused_gin<true>,
                         cudaFuncAttributeMaxDynamicSharedMemorySize, SMEM_F);
    cudaFuncSetAttribute(fused_gin_mlp,
                         cudaFuncAttributeMaxDynamicSharedMemorySize, SMEM_F);

    const int GRID = 148;
    const int tilesN = (NN + 31) / 32;   // 3125
    const int tilesE = (EO + 31) / 32;   // 18750
    const int gaN = ((unsigned)NN * 32u + 255u) / 256u;
    const int gaE = ((unsigned)EO * 32u + 255u) / 256u;

    // node layer 0: agg(x_orig) -> hB (fp16); GEMM -> hA
    gather_agg_f<<<gaN, 256>>>(x_orig, rpN, adjN, hB, NN);
    fused_gin<false><<<GRID, 512, SMEM_F>>>(
        hB, (const uint4*)W1F, (const uint4*)W2F, nullptr, nullptr,
        bfb, init_b2, nullptr, hA, nullptr, NN, tilesN);

    // node layer 1 + MLP: agg(hA) -> hC; 4-pass GEMM -> hD
    gather_agg_h<<<gaN, 256>>>(hA, rpN, adjN, hC, NN);
    fused_gin_mlp<<<GRID, 512, SMEM_F>>>(
        hC,
        (const uint4*)(W1F + 8192), (const uint4*)(W2F + 8192),
        (const uint4*)(W1F + 2 * 8192), (const uint4*)(W2F + 2 * 8192),
        bfb + HD, init_b2 + HD, bfb + 2 * HD, mlp_b2, hD, NN, tilesN);

    // edge layer 0: fused pair-lift + agg (hD L2-resident) -> heB; GEMM -> heC
    pair_agg_h<<<gaE, 256>>>(edge_pairs, hD, rpE, adjE, heB, EO);
    fused_gin<false><<<GRID, 512, SMEM_F>>>(
        heB, (const uint4*)(W1F + 3 * 8192), (const uint4*)(W2F + 3 * 8192),
        nullptr, nullptr, bfb + 3 * HD, gin_b2, nullptr, heC, nullptr, EO, tilesE);

    // edge layer 1 + head: agg(heC) -> heA; GEMM+head -> out (f32)
    gather_agg_h<<<gaE, 256>>>(heC, rpE, adjE, heA, EO);
    fused_gin<true><<<GRID, 512, SMEM_F>>>(
        heA, (const uint4*)(W1F + 4 * 8192), (const uint4*)(W2F + 4 * 8192),
        (const uint4*)Wofh, (const uint4*)Wofl,
        bfb + 4 * HD, gin_b2 + HD, out_b, nullptr, out, EO, tilesE);
}

// round 17
// speedup vs baseline: 1.4036x; 1.4036x over previous
#include <cuda_runtime.h>
#include <cuda_fp16.h>
#include <cstdint>

#define NN 100000
#define EO 600000
#define EL 1200000
#define HD 128
#define OD 64
#define SA 136   // smem row stride (fp16 elems); 272B rows, 16B aligned

// ---------------- scratch (device globals) ---------------------------------
static __device__ __half g_hA[(size_t)NN * HD];
static __device__ __half g_hB[(size_t)NN * HD];
static __device__ __half g_hC[(size_t)NN * HD];
static __device__ __half g_hD[(size_t)NN * HD];
static __device__ __half g_heA[(size_t)EO * HD];
static __device__ __half g_heB[(size_t)EO * HD];
static __device__ __half g_heC[(size_t)EO * HD];
static __device__ __half g_W1h[5][HD * HD];          // n-major fp16 images
static __device__ __half g_W2h[5][HD * HD];
static __device__ uint32_t g_W1F[5][8192];           // W1 frags (N=128)
static __device__ uint32_t g_W2F[5][8192];           // W2 frags (N=128)
static __device__ uint32_t g_Wofh[4096], g_Wofl[4096];  // Wo frags hi+lo (N=64)
static __device__ float g_bfb[5][HD];
// CSR scratch
static __device__ int g_deg[EO], g_ex[EO], g_bsum[1024];
static __device__ int g_rpN[NN + 1], g_adjN[EO], g_curN[NN];
static __device__ int g_rpE[EO + 1], g_adjE[EL], g_curE[EO];

// ---------------- PTX helpers ----------------------------------------------
__device__ __forceinline__ void ldsm4(uint32_t* r, const void* p) {
    uint32_t a = (uint32_t)__cvta_generic_to_shared(p);
    asm volatile("ldmatrix.sync.aligned.m8n8.x4.shared.b16 {%0,%1,%2,%3}, [%4];"
                 : "=r"(r[0]), "=r"(r[1]), "=r"(r[2]), "=r"(r[3]) : "r"(a));
}
__device__ __forceinline__ void stsm4(void* p, uint32_t r0, uint32_t r1,
                                      uint32_t r2, uint32_t r3) {
    uint32_t a = (uint32_t)__cvta_generic_to_shared(p);
    asm volatile("stmatrix.sync.aligned.m8n8.x4.shared.b16 [%0], {%1,%2,%3,%4};"
                 :: "r"(a), "r"(r0), "r"(r1), "r"(r2), "r"(r3) : "memory");
}
__device__ __forceinline__ void mma_f16(float* d, const uint32_t* a,
                                        uint32_t b0, uint32_t b1) {
    asm volatile(
        "mma.sync.aligned.m16n8k16.row.col.f32.f16.f16.f32 "
        "{%0,%1,%2,%3}, {%4,%5,%6,%7}, {%8,%9}, {%0,%1,%2,%3};"
        : "+f"(d[0]), "+f"(d[1]), "+f"(d[2]), "+f"(d[3])
        : "r"(a[0]), "r"(a[1]), "r"(a[2]), "r"(a[3]), "r"(b0), "r"(b1));
}
__device__ __forceinline__ void cp16(void* sdst, const void* gsrc) {
    uint32_t a = (uint32_t)__cvta_generic_to_shared(sdst);
    asm volatile("cp.async.cg.shared.global [%0], [%1], 16;"
                 :: "r"(a), "l"(gsrc) : "memory");
}
#define CP_COMMIT() asm volatile("cp.async.commit_group;" ::: "memory")
#define CP_WAIT0()  asm volatile("cp.async.wait_group 0;" ::: "memory")

__device__ __forceinline__ uint32_t packh(float a, float b) {
    __half2 t = __floats2half2_rn(a, b);
    return *(uint32_t*)&t;
}
__device__ __forceinline__ void unpackh(uint32_t v, float& a, float& b) {
    __half2 t = *(__half2*)&v;
    a = __half2float(__low2half(t));
    b = __half2float(__high2half(t));
}
#define BARQ(id) asm volatile("bar.sync %0, 128;" :: "r"(id) : "memory")

// ---------------- GEMM pass: A fp16 from smem, W single-fp16 frags ----------
__device__ __forceinline__ void gemm_pass_frag(
    const __half* As, const uint4* __restrict__ F,
    int cc, int lrow, int lkoff, int lane, float (&acc)[2][4][4]) {
#pragma unroll
    for (int mi = 0; mi < 2; ++mi)
#pragma unroll
        for (int ni = 0; ni < 4; ++ni)
#pragma unroll
            for (int q = 0; q < 4; ++q) acc[mi][ni][q] = 0.f;
#pragma unroll
    for (int ks = 0; ks < 8; ++ks) {
        const int k0 = ks * 16 + lkoff;
        uint32_t ah[2][4];
#pragma unroll
        for (int mi = 0; mi < 2; ++mi)
            ldsm4(ah[mi], As + (mi * 16 + lrow) * SA + k0);
#pragma unroll
        for (int nj = 0; nj < 2; ++nj) {
            const uint4 b = F[((cc * 2 + nj) * 8 + ks) * 32 + lane];
#pragma unroll
            for (int mi = 0; mi < 2; ++mi) {
                const int n0 = nj * 2;
                mma_f16(acc[mi][n0], ah[mi], b.x, b.z);
                mma_f16(acc[mi][n0 + 1], ah[mi], b.y, b.w);
            }
        }
    }
}

// bias+relu then stmatrix back into As (quarter rows 0..31)
__device__ __forceinline__ void epi_to_smem(
    const float (&acc)[2][4][4], const float (&br)[4][2],
    __half* As, int colBase, int lane) {
    const int srow = (lane & 7) + ((lane >> 3) & 1) * 8;
    const int scol = (lane >> 4) * 8;
#pragma unroll
    for (int mi = 0; mi < 2; ++mi) {
#pragma unroll
        for (int ng = 0; ng < 2; ++ng) {
            float v[2][4];
#pragma unroll
            for (int q = 0; q < 2; ++q) {
                const int ni = ng * 2 + q;
                v[q][0] = fmaxf(acc[mi][ni][0] + br[ni][0], 0.f);
                v[q][1] = fmaxf(acc[mi][ni][1] + br[ni][1], 0.f);
                v[q][2] = fmaxf(acc[mi][ni][2] + br[ni][0], 0.f);
                v[q][3] = fmaxf(acc[mi][ni][3] + br[ni][1], 0.f);
            }
            const int off = (mi * 16 + srow) * SA + colBase + ng * 16 + scol;
            stsm4(As + off, packh(v[0][0], v[0][1]), packh(v[0][2], v[0][3]),
                  packh(v[1][0], v[1][1]), packh(v[1][2], v[1][3]));
        }
    }
}

// gmem write: acc + bias + relu -> C [M,HD] as fp16
__device__ __forceinline__ void write_outh(
    const float (&acc)[2][4][4], const float (&br)[4][2],
    __half* __restrict__ C, int m0, int colBase, int cq, int rq, int M) {
#pragma unroll
    for (int mi = 0; mi < 2; ++mi)
#pragma unroll
        for (int ni = 0; ni < 4; ++ni) {
            const int col = colBase + ni * 8 + cq;
            const int r0 = m0 + mi * 16 + rq, r1 = r0 + 8;
            float v00 = fmaxf(acc[mi][ni][0] + br[ni][0], 0.f);
            float v01 = fmaxf(acc[mi][ni][1] + br[ni][1], 0.f);
            float v10 = fmaxf(acc[mi][ni][2] + br[ni][0], 0.f);
            float v11 = fmaxf(acc[mi][ni][3] + br[ni][1], 0.f);
            if (r0 < M) *(uint32_t*)(C + (size_t)r0 * HD + col) = packh(v00, v01);
            if (r1 < M) *(uint32_t*)(C + (size_t)r1 * HD + col) = packh(v10, v11);
        }
}

// smem: per quarter: two ping-pong As buffers (8704 B each) = 17408; x4
#define QSZ    17408
#define SMEM_F 69632

// cp.async a 32-row fp16 tile straight into ldsm layout (row*SA)
__device__ __forceinline__ void issue_cp_tileh(const __half* __restrict__ A,
                                               __half* Asdst, int tile, int M,
                                               int tiq) {
#pragma unroll
    for (int qq = 0; qq < 4; ++qq) {
        const int i = tiq + 128 * qq;         // 0..511
        const int r = i >> 4, c = i & 15;     // 16 x 16B chunks per 256B row
        const int grow = tile * 32 + r;
        __half* dst = Asdst + r * SA + c * 8;
        if (grow < M)
            cp16(dst, A + (size_t)grow * HD + c * 8);
        else
            *(uint4*)dst = make_uint4(0, 0, 0, 0);
    }
}

// ---------------- fused GIN layer: 4 independent quarter-pipelines ----------
// HEAD=false: out fp16 [M,HD]; HEAD=true: third GEMM vs Wo (hi+lo), out f32
template <bool HEAD>
__global__ __launch_bounds__(512, 1) void fused_gin(
    const __half* __restrict__ A,
    const uint4* __restrict__ W1F, const uint4* __restrict__ W2F,
    const uint4* __restrict__ WoFh, const uint4* __restrict__ WoFl,
    const float* __restrict__ b1, const float* __restrict__ b2,
    const float* __restrict__ b3,
    __half* __restrict__ C, float* __restrict__ Cf, int M, int nTiles) {
    extern __shared__ char smem[];
    const int tid = threadIdx.x, lane = tid & 31, wid = tid >> 5;
    const int q = wid >> 2, cc = wid & 3, tiq = tid & 127;

    __half* As0 = (__half*)(smem + q * QSZ);
    __half* As1 = As0 + 32 * SA;

    const int barid = 1 + q;
    const int colBase = cc * 32;
    const int lrow = lane & 15, lkoff = (lane >> 4) * 8;
    const int cq = (lane & 3) * 2, rq = lane >> 2;

    float b1r[4][2], b2r[4][2], b3r[2][2];
#pragma unroll
    for (int ni = 0; ni < 4; ++ni) {
        const int col = colBase + ni * 8 + cq;
        b1r[ni][0] = b1[col]; b1r[ni][1] = b1[col + 1];
        b2r[ni][0] = b2[col]; b2r[ni][1] = b2[col + 1];
    }
    if (HEAD) {
#pragma unroll
        for (int ni = 0; ni < 2; ++ni) {
            const int col = cc * 16 + ni * 8 + cq;
            b3r[ni][0] = b3[col]; b3r[ni][1] = b3[col + 1];
        }
    }

    int tile = blockIdx.x * 4 + q;
    int pb = 0;
    if (tile < nTiles) issue_cp_tileh(A, As0, tile, M, tiq);
    CP_COMMIT();

    for (; tile < nTiles; tile += gridDim.x * 4) {
        const int m0 = tile * 32;
        __half* Asb = pb ? As1 : As0;
        __half* Aso = pb ? As0 : As1;
        CP_WAIT0();
        BARQ(barid);   // this tile's A landed; previous iteration fully done

        const int nxt = tile + gridDim.x * 4;
        if (nxt < nTiles) issue_cp_tileh(A, Aso, nxt, M, tiq);
        CP_COMMIT();

        float acc[2][4][4];
        gemm_pass_frag(Asb, W1F, cc, lrow, lkoff, lane, acc);
        BARQ(barid);
        epi_to_smem(acc, b1r, Asb, colBase, lane);
        BARQ(barid);
        gemm_pass_frag(Asb, W2F, cc, lrow, lkoff, lane, acc);

        if (!HEAD) {
            write_outh(acc, b2r, C, m0, colBase, cq, rq, M);
        } else {
            BARQ(barid);
            epi_to_smem(acc, b2r, Asb, colBase, lane);
            BARQ(barid);
            float acc3[2][2][4];
#pragma unroll
            for (int mi = 0; mi < 2; ++mi)
#pragma unroll
                for (int ni = 0; ni < 2; ++ni)
#pragma unroll
                    for (int p = 0; p < 4; ++p) acc3[mi][ni][p] = 0.f;
#pragma unroll
            for (int ks = 0; ks < 8; ++ks) {
                const int k0 = ks * 16 + lkoff;
                uint32_t ah[2][4];
#pragma unroll
                for (int mi = 0; mi < 2; ++mi)
                    ldsm4(ah[mi], Asb + (mi * 16 + lrow) * SA + k0);
                const uint4 bh = WoFh[(cc * 8 + ks) * 32 + lane];
                const uint4 bl = WoFl[(cc * 8 + ks) * 32 + lane];
#pragma unroll
                for (int mi = 0; mi < 2; ++mi) {
                    mma_f16(acc3[mi][0], ah[mi], bh.x, bh.z);
                    mma_f16(acc3[mi][0], ah[mi], bl.x, bl.z);
                    mma_f16(acc3[mi][1], ah[mi], bh.y, bh.w);
                    mma_f16(acc3[mi][1], ah[mi], bl.y, bl.w);
                }
            }
#pragma unroll
            for (int mi = 0; mi < 2; ++mi)
#pragma unroll
                for (int ni = 0; ni < 2; ++ni) {
                    const int col = cc * 16 + ni * 8 + cq;
                    const int r0 = m0 + mi * 16 + rq, r1 = r0 + 8;
                    if (r0 < M)
                        *(float2*)(Cf + (size_t)r0 * OD + col) = make_float2(
                            acc3[mi][ni][0] + b3r[ni][0], acc3[mi][ni][1] + b3r[ni][1]);
                    if (r1 < M)
                        *(float2*)(Cf + (size_t)r1 * OD + col) = make_float2(
                            acc3[mi][ni][2] + b3r[ni][0], acc3[mi][ni][3] + b3r[ni][1]);
                }
        }
        pb ^= 1;
    }
}

// ---------------- fused node layer 1 + MLP (4 passes) ----------------------
__global__ __launch_bounds__(512, 1) void fused_gin_mlp(
    const __half* __restrict__ A,
    const uint4* __restrict__ WaF, const uint4* __restrict__ WbF,
    const uint4* __restrict__ WcF, const uint4* __restrict__ WdF,
    const float* __restrict__ b1, const float* __restrict__ b2,
    const float* __restrict__ b3, const float* __restrict__ b4,
    __half* __restrict__ C, int M, int nTiles) {
    extern __shared__ char smem[];
    const int tid = threadIdx.x, lane = tid & 31, wid = tid >> 5;
    const int q = wid >> 2, cc = wid & 3, tiq = tid & 127;

    __half* As0 = (__half*)(smem + q * QSZ);
    __half* As1 = As0 + 32 * SA;

    const int barid = 1 + q;
    const int colBase = cc * 32;
    const int lrow = lane & 15, lkoff = (lane >> 4) * 8;
    const int cq = (lane & 3) * 2, rq = lane >> 2;

    float b1r[4][2], b2r[4][2], b3r[4][2], b4r[4][2];
#pragma unroll
    for (int ni = 0; ni < 4; ++ni) {
        const int col = colBase + ni * 8 + cq;
        b1r[ni][0] = b1[col]; b1r[ni][1] = b1[col + 1];
        b2r[ni][0] = b2[col]; b2r[ni][1] = b2[col + 1];
        b3r[ni][0] = b3[col]; b3r[ni][1] = b3[col + 1];
        b4r[ni][0] = b4[col]; b4r[ni][1] = b4[col + 1];
    }

    int tile = blockIdx.x * 4 + q;
    int pb = 0;
    if (tile < nTiles) issue_cp_tileh(A, As0, tile, M, tiq);
    CP_COMMIT();

    for (; tile < nTiles; tile += gridDim.x * 4) {
        const int m0 = tile * 32;
        __half* Asb = pb ? As1 : As0;
        __half* Aso = pb ? As0 : As1;
        CP_WAIT0();
        BARQ(barid);

        const int nxt = tile + gridDim.x * 4;
        if (nxt < nTiles) issue_cp_tileh(A, Aso, nxt, M, tiq);
        CP_COMMIT();

        float acc[2][4][4];
        gemm_pass_frag(Asb, WaF, cc, lrow, lkoff, lane, acc);
        BARQ(barid);
        epi_to_smem(acc, b1r, Asb, colBase, lane);
        BARQ(barid);
        gemm_pass_frag(Asb, WbF, cc, lrow, lkoff, lane, acc);
        BARQ(barid);
        epi_to_smem(acc, b2r, Asb, colBase, lane);   // layer out (relu)
        BARQ(barid);
        gemm_pass_frag(Asb, WcF, cc, lrow, lkoff, lane, acc);
        BARQ(barid);
        epi_to_smem(acc, b3r, Asb, colBase, lane);   // mlp hidden (relu)
        BARQ(barid);
        gemm_pass_frag(Asb, WdF, cc, lrow, lkoff, lane, acc);
        // mlp out (no relu) -> fp16
#pragma unroll
        for (int mi = 0; mi < 2; ++mi)
#pragma unroll
            for (int ni = 0; ni < 4; ++ni) {
                const int col = colBase + ni * 8 + cq;
                const int r0 = m0 + mi * 16 + rq, r1 = r0 + 8;
                if (r0 < M)
                    *(uint32_t*)(C + (size_t)r0 * HD + col) =
                        packh(acc[mi][ni][0] + b4r[ni][0], acc[mi][ni][1] + b4r[ni][1]);
                if (r1 < M)
                    *(uint32_t*)(C + (size_t)r1 * HD + col) =
                        packh(acc[mi][ni][2] + b4r[ni][0], acc[mi][ni][3] + b4r[ni][1]);
            }
        pb ^= 1;
    }
}

// ---------------- weight prep ------------------------------------------------
struct PrepArgs {
    const float *W1[5], *b1[5], *g[5], *bb[5], *m[5], *v[5], *W2[5], *Wo;
    __half *W1h[5], *W2h[5];
    uint32_t *Wofh, *Wofl;
    float* bf[5];
};

__global__ void prep_weights(PrepArgs a) {
    const int blk = blockIdx.x, tid = threadIdx.x;
    if (blk < 320) {
        const int j = blk >> 6;
        const int idx = ((blk & 63) << 8) + tid;
        const int k = idx >> 7, n = idx & 127;
        float s = a.g[j][n] * rsqrtf(a.v[j][n] + 1e-5f);
        a.W1h[j][n * 128 + k] = __float2half(a.W1[j][idx] * s);
        if (idx < 128)
            a.bf[j][idx] = a.b1[j][idx] * s + a.bb[j][idx] - a.m[j][idx] * s;
    } else if (blk < 640) {
        const int j = (blk - 320) >> 6;
        const int idx = (((blk - 320) & 63) << 8) + tid;
        const int k = idx >> 7, n = idx & 127;
        a.W2h[j][n * 128 + k] = __float2half(a.W2[j][idx]);
    } else {
        const int idx = ((blk - 640) << 8) + tid;  // 0..4095 (Wo frags hi+lo)
        const int j = idx & 3, L = (idx >> 2) & 31;
        const int ks = (idx >> 7) & 7, cc = idx >> 10;
        const int n = cc * 16 + (j & 1) * 8 + (L >> 2);
        const int k = ks * 16 + ((j >> 1)) * 8 + (L & 3) * 2;
        float v0 = a.Wo[k * OD + n];
        float v1 = a.Wo[(k + 1) * OD + n];
        __half h0 = __float2half(v0), h1 = __float2half(v1);
        __half l0 = __float2half(v0 - __half2float(h0));
        __half l1 = __float2half(v1 - __half2float(h1));
        __half2 th = __halves2half2(h0, h1), tl = __halves2half2(l0, l1);
        a.Wofh[((cc * 8 + ks) * 32 + L) * 4 + j] = *(uint32_t*)&th;
        a.Wofl[((cc * 8 + ks) * 32 + L) * 4 + j] = *(uint32_t*)&tl;
    }
}

struct FragArgs {
    const __half* src[10];
    uint32_t* dst[10];
};
__global__ void frag_all(FragArgs a) {
    const int i = blockIdx.x * 256 + threadIdx.x;   // 0..81919
    const int m = i >> 13, e = i & 8191;
    const int j = e & 3, L = (e >> 2) & 31;
    const int ks = (e >> 7) & 7, g = e >> 10;
    const int n = g * 16 + (j & 1) * 8 + (L >> 2);
    const int k = ks * 16 + (j >> 1) * 8 + (L & 3) * 2;
    a.dst[m][e] = *(const uint32_t*)(a.src[m] + n * 128 + k);
}

// ---------------- CSR build ----------------------------------------------------
__global__ void count_deg(const int* __restrict__ dst, int E, int* __restrict__ deg) {
    int e = blockIdx.x * 256 + threadIdx.x;
    if (e < E) atomicAdd(&deg[dst[e]], 1);
}

__global__ void scan1(const int* __restrict__ deg, int* __restrict__ ex,
                      int* __restrict__ bsum, int n) {
    __shared__ int wsum[32];
    const int t = threadIdx.x;
    const int base = blockIdx.x * 4096 + t * 4;
    int v[4], s = 0;
#pragma unroll
    for (int i = 0; i < 4; ++i) {
        int idx = base + i;
        v[i] = idx < n ? deg[idx] : 0;
        s += v[i];
    }
    const int lane = t & 31, w = t >> 5;
    int ps = s;
#pragma unroll
    for (int o = 1; o < 32; o <<= 1) {
        int y = __shfl_up_sync(~0u, ps, o);
        if (lane >= o) ps += y;
    }
    if (lane == 31) wsum[w] = ps;
    __syncthreads();
    if (w == 0) {
        int x = wsum[lane];
#pragma unroll
        for (int o = 1; o < 32; o <<= 1) {
            int y = __shfl_up_sync(~0u, x, o);
            if (lane >= o) x += y;
        }
        wsum[lane] = x;
    }
    __syncthreads();
    const int warpoff = w ? wsum[w - 1] : 0;
    int run = warpoff + ps - s;
#pragma unroll
    for (int i = 0; i < 4; ++i) {
        int idx = base + i;
        if (idx < n) ex[idx] = run;
        run += v[i];
    }
    if (t == 0) bsum[blockIdx.x] = wsum[31];
}

__global__ void scan2(int* __restrict__ bsum, int nb) {
    __shared__ int sm_[1024];
    const int t = threadIdx.x;
    int v = (t < nb) ? bsum[t] : 0;
    sm_[t] = v;
    __syncthreads();
    for (int o = 1; o < 1024; o <<= 1) {
        int y = (t >= o) ? sm_[t - o] : 0;
        __syncthreads();
        sm_[t] += y;
        __syncthreads();
    }
    if (t < nb) bsum[t] = sm_[t] - v;
}

__global__ void scan3(const int* __restrict__ ex, const int* __restrict__ boff,
                      int* __restrict__ rp, int* __restrict__ cur, int n, int E) {
    int i = blockIdx.x * 1024 + threadIdx.x;
    if (i < n) {
        int vv = ex[i] + boff[i >> 12];
        rp[i] = vv;
        cur[i] = vv;
    } else if (i == n) {
        rp[n] = E;
    }
}

__global__ void fill_csr(const int* __restrict__ src, const int* __restrict__ dst,
                         int E, int* __restrict__ cur, int* __restrict__ adj) {
    int e = blockIdx.x * 256 + threadIdx.x;
    if (e < E) {
        int p = atomicAdd(&cur[dst[e]], 1);
        adj[p] = src[e];
    }
}

// ---------------- gather aggregation (fp16 rows, f32 accumulate) --------------
__device__ __forceinline__ void addrow_h(const __half* __restrict__ x, int row,
                                         int lane, float (&acc)[4]) {
    uint2 u = *(const uint2*)(x + (size_t)row * HD + lane * 4);
    float a0, a1, a2, a3;
    unpackh(u.x, a0, a1);
    unpackh(u.y, a2, a3);
    acc[0] += a0; acc[1] += a1; acc[2] += a2; acc[3] += a3;
}

// first layer: x f32, out fp16
__global__ void gather_agg_f(const float* __restrict__ x,
                             const int* __restrict__ rp,
                             const int* __restrict__ adj,
                             __half* __restrict__ agg, int n) {
    unsigned t = blockIdx.x * 256u + threadIdx.x;
    unsigned r = t >> 5, lane = t & 31u;
    if (r >= (unsigned)n) return;
    const int s = rp[r], e = rp[r + 1];
    float4 acc = ((const float4*)(x + (size_t)r * HD))[lane];
    const int cnt = e - s;
    int nb_l = ((int)lane < cnt) ? adj[s + lane] : 0;
    const int lim = cnt < 32 ? cnt : 32;
    for (int j = 0; j < lim; ++j) {
        const int nb = __shfl_sync(~0u, nb_l, j);
        float4 u = ((const float4*)(x + (size_t)nb * HD))[lane];
        acc.x += u.x; acc.y += u.y; acc.z += u.z; acc.w += u.w;
    }
    for (int j = s + 32; j < e; ++j) {
        const int nb = adj[j];
        float4 u = ((const float4*)(x + (size_t)nb * HD))[lane];
        acc.x += u.x; acc.y += u.y; acc.z += u.z; acc.w += u.w;
    }
    *(uint2*)(agg + (size_t)r * HD + lane * 4) =
        make_uint2(packh(acc.x, acc.y), packh(acc.z, acc.w));
}

// fp16 in, fp16 out
__global__ void gather_agg_h(const __half* __restrict__ x,
                             const int* __restrict__ rp,
                             const int* __restrict__ adj,
                             __half* __restrict__ agg, int n) {
    unsigned t = blockIdx.x * 256u + threadIdx.x;
    unsigned r = t >> 5, lane = t & 31u;
    if (r >= (unsigned)n) return;
    const int s = rp[r], e = rp[r + 1];
    float acc[4] = {0.f, 0.f, 0.f, 0.f};
    addrow_h(x, r, lane, acc);
    const int cnt = e - s;
    int nb_l = ((int)lane < cnt) ? adj[s + lane] : 0;
    const int lim = cnt < 32 ? cnt : 32;
    for (int j = 0; j < lim; ++j) {
        const int nb = __shfl_sync(~0u, nb_l, j);
        addrow_h(x, nb, lane, acc);
    }
    for (int j = s + 32; j < e; ++j) addrow_h(x, adj[j], lane, acc);
    *(uint2*)(agg + (size_t)r * HD + lane * 4) =
        make_uint2(packh(acc[0], acc[1]), packh(acc[2], acc[3]));
}

// fused pair lift + aggregation (fp16 y, L2-resident)
__global__ void pair_agg_h(const int* __restrict__ ep,
                           const __half* __restrict__ y,
                           const int* __restrict__ rp,
                           const int* __restrict__ adj,
                           __half* __restrict__ agg, int n) {
    unsigned t = blockIdx.x * 256u + threadIdx.x;
    unsigned r = t >> 5, lane = t & 31u;
    if (r >= (unsigned)n) return;
    const int s = rp[r], e = rp[r + 1];
    const int cnt = e - s;
    float acc[4] = {0.f, 0.f, 0.f, 0.f};
    addrow_h(y, ep[2 * r], lane, acc);
    addrow_h(y, ep[2 * r + 1], lane, acc);
    int p0_l = 0, p1_l = 0;
    if ((int)lane < cnt) {
        const int nb = adj[s + lane];
        p0_l = ep[2 * nb];
        p1_l = ep[2 * nb + 1];
    }
    const int lim = cnt < 32 ? cnt : 32;
    for (int j = 0; j < lim; ++j) {
        addrow_h(y, __shfl_sync(~0u, p0_l, j), lane, acc);
        addrow_h(y, __shfl_sync(~0u, p1_l, j), lane, acc);
    }
    for (int j = s + 32; j < e; ++j) {
        const int nb = adj[j];
        addrow_h(y, ep[2 * nb], lane, acc);
        addrow_h(y, ep[2 * nb + 1], lane, acc);
    }
    *(uint2*)(agg + (size_t)r * HD + lane * 4) =
        make_uint2(packh(acc[0], acc[1]), packh(acc[2], acc[3]));
}

// ----------------------------------------------------------------------------------
extern "C" void kernel_launch(void* const* d_in, const int* in_sizes, int n_in,
                              void* d_out, int out_size) {
    const int*   edge_index = (const int*)d_in[0];
    const float* x_orig     = (const float*)d_in[1];
    const int*   ei_orig    = (const int*)d_in[2];
    const int*   edge_pairs = (const int*)d_in[3];
    const float* init_W1 = (const float*)d_in[4];
    const float* init_b1 = (const float*)d_in[5];
    const float* init_g  = (const float*)d_in[6];
    const float* init_bb = (const float*)d_in[7];
    const float* init_m  = (const float*)d_in[8];
    const float* init_v  = (const float*)d_in[9];
    const float* init_W2 = (const float*)d_in[10];
    const float* init_b2 = (const float*)d_in[11];
    const float* gin_W1  = (const float*)d_in[12];
    const float* gin_b1  = (const float*)d_in[13];
    const float* gin_g   = (const float*)d_in[14];
    const float* gin_bb  = (const float*)d_in[15];
    const float* gin_m   = (const float*)d_in[16];
    const float* gin_v   = (const float*)d_in[17];
    const float* gin_W2  = (const float*)d_in[18];
    const float* gin_b2  = (const float*)d_in[19];
    const float* mlp_W1  = (const float*)d_in[20];
    const float* mlp_b1  = (const float*)d_in[21];
    const float* mlp_g   = (const float*)d_in[22];
    const float* mlp_bb  = (const float*)d_in[23];
    const float* mlp_m   = (const float*)d_in[24];
    const float* mlp_v   = (const float*)d_in[25];
    const float* mlp_W2  = (const float*)d_in[26];
    const float* mlp_b2  = (const float*)d_in[27];
    const float* out_W   = (const float*)d_in[28];
    const float* out_b   = (const float*)d_in[29];
    float* out = (float*)d_out;

    __half *hA, *hB, *hC, *hD, *heA, *heB, *heC;
    __half *W1h, *W2h;
    uint32_t *W1F, *W2F, *Wofh, *Wofl;
    float* bfb;
    int *deg, *ex, *bsum, *rpN, *adjN, *curN, *rpE, *adjE, *curE;
    cudaGetSymbolAddress((void**)&hA, g_hA);
    cudaGetSymbolAddress((void**)&hB, g_hB);
    cudaGetSymbolAddress((void**)&hC, g_hC);
    cudaGetSymbolAddress((void**)&hD, g_hD);
    cudaGetSymbolAddress((void**)&heA, g_heA);
    cudaGetSymbolAddress((void**)&heB, g_heB);
    cudaGetSymbolAddress((void**)&heC, g_heC);
    cudaGetSymbolAddress((void**)&bfb, g_bfb);
    cudaGetSymbolAddress((void**)&W1h, g_W1h);
    cudaGetSymbolAddress((void**)&W2h, g_W2h);
    cudaGetSymbolAddress((void**)&W1F, g_W1F);
    cudaGetSymbolAddress((void**)&W2F, g_W2F);
    cudaGetSymbolAddress((void**)&Wofh, g_Wofh);
    cudaGetSymbolAddress((void**)&Wofl, g_Wofl);
    cudaGetSymbolAddress((void**)&deg, g_deg);
    cudaGetSymbolAddress((void**)&ex, g_ex);
    cudaGetSymbolAddress((void**)&bsum, g_bsum);
    cudaGetSymbolAddress((void**)&rpN, g_rpN);
    cudaGetSymbolAddress((void**)&adjN, g_adjN);
    cudaGetSymbolAddress((void**)&curN, g_curN);
    cudaGetSymbolAddress((void**)&rpE, g_rpE);
    cudaGetSymbolAddress((void**)&adjE, g_adjE);
    cudaGetSymbolAddress((void**)&curE, g_curE);

    // ---- weight prep --------------------------------------------------------
    PrepArgs pa;
    const float* W1s[5]  = {init_W1, init_W1 + HD * HD, mlp_W1, gin_W1, gin_W1 + HD * HD};
    const float* b1s[5]  = {init_b1, init_b1 + HD, mlp_b1, gin_b1, gin_b1 + HD};
    const float* gs[5]   = {init_g, init_g + HD, mlp_g, gin_g, gin_g + HD};
    const float* bbs[5]  = {init_bb, init_bb + HD, mlp_bb, gin_bb, gin_bb + HD};
    const float* ms[5]   = {init_m, init_m + HD, mlp_m, gin_m, gin_m + HD};
    const float* vs[5]   = {init_v, init_v + HD, mlp_v, gin_v, gin_v + HD};
    const float* W2s[5]  = {init_W2, init_W2 + HD * HD, mlp_W2, gin_W2, gin_W2 + HD * HD};
    for (int j = 0; j < 5; ++j) {
        pa.W1[j] = W1s[j]; pa.b1[j] = b1s[j]; pa.g[j] = gs[j]; pa.bb[j] = bbs[j];
        pa.m[j] = ms[j]; pa.v[j] = vs[j]; pa.W2[j] = W2s[j];
        pa.W1h[j] = W1h + (size_t)j * HD * HD;
        pa.W2h[j] = W2h + (size_t)j * HD * HD;
        pa.bf[j] = bfb + j * HD;
    }
    pa.Wo = out_W; pa.Wofh = Wofh; pa.Wofl = Wofl;
    prep_weights<<<656, 256>>>(pa);

    FragArgs fa;
    for (int j = 0; j < 5; ++j) {
        fa.src[j]     = W1h + (size_t)j * HD * HD; fa.dst[j]     = W1F + (size_t)j * 8192;
        fa.src[5 + j] = W2h + (size_t)j * HD * HD; fa.dst[5 + j] = W2F + (size_t)j * 8192;
    }
    frag_all<<<320, 256>>>(fa);

    // ---- CSR build: node graph --------------------------------------------
    cudaMemsetAsync(deg, 0, NN * sizeof(int));
    count_deg<<<(EO + 255) / 256, 256>>>(ei_orig + EO, EO, deg);
    scan1<<<(NN + 4095) / 4096, 1024>>>(deg, ex, bsum, NN);
    scan2<<<1, 1024>>>(bsum, (NN + 4095) / 4096);
    scan3<<<(NN + 1024) / 1024 + 1, 1024>>>(ex, bsum, rpN, curN, NN, EO);
    fill_csr<<<(EO + 255) / 256, 256>>>(ei_orig, ei_orig + EO, EO, curN, adjN);

    // ---- CSR build: line graph --------------------------------------------
    cudaMemsetAsync(deg, 0, EO * sizeof(int));
    count_deg<<<(EL + 255) / 256, 256>>>(edge_index + EL, EL, deg);
    scan1<<<(EO + 4095) / 4096, 1024>>>(deg, ex, bsum, EO);
    scan2<<<1, 1024>>>(bsum, (EO + 4095) / 4096);
    scan3<<<(EO + 1024) / 1024 + 1, 1024>>>(ex, bsum, rpE, curE, EO, EL);
    fill_csr<<<(EL + 255) / 256, 256>>>(edge_index, edge_index + EL, EL, curE, adjE);

    // ---- main pipeline ------------------------------------------------------
    cudaFuncSetAttribute(fused_gin<false>,
                         cudaFuncAttributeMaxDynamicSharedMemorySize, SMEM_F);
    cudaFuncSetAttribute(fused_gin<true>,
                         cudaFuncAttributeMaxDynamicSharedMemorySize, SMEM_F);
    cudaFuncSetAttribute(fused_gin_mlp,
                         cudaFuncAttributeMaxDynamicSharedMemorySize, SMEM_F);

    const int GRID = 148;
    const int tilesN = (NN + 31) / 32;   // 3125
    const int tilesE = (EO + 31) / 32;   // 18750
    const int gaN = ((unsigned)NN * 32u + 255u) / 256u;
    const int gaE = ((unsigned)EO * 32u + 255u) / 256u;

    // node layer 0: agg(x_orig) -> hB (fp16); GEMM -> hA
    gather_agg_f<<<gaN, 256>>>(x_orig, rpN, adjN, hB, NN);
    fused_gin<false><<<GRID, 512, SMEM_F>>>(
        hB, (const uint4*)W1F, (const uint4*)W2F, nullptr, nullptr,
        bfb, init_b2, nullptr, hA, nullptr, NN, tilesN);

    // node layer 1 + MLP: agg(hA) -> hC; 4-pass GEMM -> hD
    gather_agg_h<<<gaN, 256>>>(hA, rpN, adjN, hC, NN);
    fused_gin_mlp<<<GRID, 512, SMEM_F>>>(
        hC,
        (const uint4*)(W1F + 8192), (const uint4*)(W2F + 8192),
        (const uint4*)(W1F + 2 * 8192), (const uint4*)(W2F + 2 * 8192),
        bfb + HD, init_b2 + HD, bfb + 2 * HD, mlp_b2, hD, NN, tilesN);

    // edge layer 0: fused pair-lift + agg (hD L2-resident) -> heB; GEMM -> heC
    pair_agg_h<<<gaE, 256>>>(edge_pairs, hD, rpE, adjE, heB, EO);
    fused_gin<false><<<GRID, 512, SMEM_F>>>(
        heB, (const uint4*)(W1F + 3 * 8192), (const uint4*)(W2F + 3 * 8192),
        nullptr, nullptr, bfb + 3 * HD, gin_b2, nullptr, heC, nullptr, EO, tilesE);

    // edge layer 1 + head: agg(heC) -> heA; GEMM+head -> out (f32)
    gather_agg_h<<<gaE, 256>>>(heC, rpE, adjE, heA, EO);
    fused_gin<true><<<GRID, 512, SMEM_F>>>(
        heA, (const uint4*)(W1F + 4 * 8192), (const uint4*)(W2F + 4 * 8192),
        (const uint4*)Wofh, (const uint4*)Wofl,
        bfb + 4 * HD, gin_b2 + HD, out_b, nullptr, out, EO, tilesE);
}